// round 1
// baseline (speedup 1.0000x reference)
#include <cuda_runtime.h>
#include <cstdint>

#define B_   4
#define S_   2048
#define HID_ 1024
#define NHD_ 1024
#define EPS_ 1e-6f

// Scratch (allocation-free rule: device globals only)
__device__ float g_value[(size_t)B_ * S_ * NHD_];   // 32 MB
__device__ float g_inv[B_ * S_];                    // 1/(eps + causal rowsum)

// ---------------------------------------------------------------------------
// Kernel 1: causal row sums of attn -> g_inv
// ---------------------------------------------------------------------------
__global__ __launch_bounds__(256) void rowsum_kernel(const float* __restrict__ attn) {
    int row = blockIdx.x;              // b*S + q
    int q   = row & (S_ - 1);
    const float* a = attn + (size_t)row * S_;   // [B,S,S] flattened: row-major works
    float s = 0.f;
    for (int k = threadIdx.x; k <= q; k += 256) s += a[k];
    #pragma unroll
    for (int off = 16; off; off >>= 1) s += __shfl_down_sync(0xffffffffu, s, off);
    __shared__ float red[8];
    if ((threadIdx.x & 31) == 0) red[threadIdx.x >> 5] = s;
    __syncthreads();
    if (threadIdx.x == 0) {
        float t = 0.f;
        #pragma unroll
        for (int i = 0; i < 8; i++) t += red[i];
        g_inv[row] = 1.f / (EPS_ + t);
    }
}

// ---------------------------------------------------------------------------
// f32x2 packed-FMA helpers (sm_103a: FFMA2 is 2x throughput of 3-reg FFMA)
// ---------------------------------------------------------------------------
__device__ __forceinline__ void fma2(unsigned long long& d,
                                     unsigned long long a,
                                     unsigned long long b) {
    asm("fma.rn.f32x2 %0, %1, %2, %0;" : "+l"(d) : "l"(a), "l"(b));
}
__device__ __forceinline__ unsigned long long pack_dup(float m) {
    unsigned long long r;
    asm("mov.b64 %0, {%1, %1};" : "=l"(r) : "r"(__float_as_int(m)));
    return r;
}

// ---------------------------------------------------------------------------
// Kernel 2: value = hidden @ Wv + bv   (M=8192, N=1024, K=1024) -> g_value
// 128x128 tile, BK=8, 256 threads, 8x8 per thread, N-paired f32x2 accumulators
// ---------------------------------------------------------------------------
__global__ __launch_bounds__(256) void sgemm_value(const float* __restrict__ A,
                                                   const float* __restrict__ W,
                                                   const float* __restrict__ bias) {
    const int N = NHD_, K = HID_;
    __shared__ __align__(16) float As[8][128];
    __shared__ __align__(16) float Bs[8][128];

    int tid = threadIdx.x;
    int bx = blockIdx.x, by = blockIdx.y;
    int tx = tid & 15, ty = tid >> 4;

    const float* Aptr = A + (size_t)(by * 128) * K;
    const float* Bptr = W + bx * 128;
    float*       Cptr = g_value + (size_t)(by * 128) * N + bx * 128;

    int aRow = tid >> 1, aCol = (tid & 1) * 4;
    int bRow = tid >> 5, bCol = (tid & 31) * 4;

    unsigned long long acc[8][4];
    #pragma unroll
    for (int i = 0; i < 8; i++)
        #pragma unroll
        for (int j = 0; j < 4; j++) acc[i][j] = 0ull;

    for (int kt = 0; kt < K; kt += 8) {
        float4 av = *reinterpret_cast<const float4*>(Aptr + (size_t)aRow * K + kt + aCol);
        As[aCol + 0][aRow] = av.x;
        As[aCol + 1][aRow] = av.y;
        As[aCol + 2][aRow] = av.z;
        As[aCol + 3][aRow] = av.w;
        *reinterpret_cast<float4*>(&Bs[bRow][bCol]) =
            *reinterpret_cast<const float4*>(Bptr + (size_t)(kt + bRow) * N + bCol);
        __syncthreads();
        #pragma unroll
        for (int kk = 0; kk < 8; kk++) {
            const unsigned long long* Bs2 =
                reinterpret_cast<const unsigned long long*>(&Bs[kk][tx * 8]);
            unsigned long long rn[4];
            #pragma unroll
            for (int j = 0; j < 4; j++) rn[j] = Bs2[j];
            #pragma unroll
            for (int i = 0; i < 8; i++) {
                unsigned long long m2 = pack_dup(As[kk][ty * 8 + i]);
                #pragma unroll
                for (int j = 0; j < 4; j++) fma2(acc[i][j], m2, rn[j]);
            }
        }
        __syncthreads();
    }

    #pragma unroll
    for (int i = 0; i < 8; i++) {
        int row = ty * 8 + i;
        #pragma unroll
        for (int j = 0; j < 4; j++) {
            float2 v = *reinterpret_cast<float2*>(&acc[i][j]);
            int col = tx * 8 + j * 2;
            v.x += bias[bx * 128 + col];
            v.y += bias[bx * 128 + col + 1];
            *reinterpret_cast<float2*>(Cptr + (size_t)row * N + col) = v;
        }
    }
}

// ---------------------------------------------------------------------------
// Kernel 3: out[b] = norm_causal(attn[b]) @ value[b]
// (per batch: M=2048, N=1024, K<=q+1 causal). Mask+scale fused into A load,
// k-loop truncated at the block's diagonal.
// ---------------------------------------------------------------------------
__global__ __launch_bounds__(256) void sgemm_attn(const float* __restrict__ attn,
                                                  float* __restrict__ out) {
    const int N = NHD_;
    int b  = blockIdx.z;
    const float* A = attn + (size_t)b * S_ * S_;
    const float* V = g_value + (size_t)b * S_ * NHD_;
    float*       C = out + (size_t)b * S_ * NHD_;
    const float* inv = g_inv + b * S_;

    __shared__ __align__(16) float As[8][128];
    __shared__ __align__(16) float Bs[8][128];

    int tid = threadIdx.x;
    int bx = blockIdx.x, by = blockIdx.y;
    int tx = tid & 15, ty = tid >> 4;

    int aRow = tid >> 1, aCol = (tid & 1) * 4;
    int bRow = tid >> 5, bCol = (tid & 31) * 4;

    int aRowG = by * 128 + aRow;
    float sc = inv[aRowG];
    const float* Arow = A + (size_t)aRowG * S_;

    unsigned long long acc[8][4];
    #pragma unroll
    for (int i = 0; i < 8; i++)
        #pragma unroll
        for (int j = 0; j < 4; j++) acc[i][j] = 0ull;

    int kend = by * 128 + 128;   // causal: no k-tiles beyond the diagonal block
    for (int kt = 0; kt < kend; kt += 8) {
        int k0 = kt + aCol;
        float4 av = *reinterpret_cast<const float4*>(Arow + k0);
        av.x = (k0 + 0 <= aRowG) ? av.x * sc : 0.f;
        av.y = (k0 + 1 <= aRowG) ? av.y * sc : 0.f;
        av.z = (k0 + 2 <= aRowG) ? av.z * sc : 0.f;
        av.w = (k0 + 3 <= aRowG) ? av.w * sc : 0.f;
        As[aCol + 0][aRow] = av.x;
        As[aCol + 1][aRow] = av.y;
        As[aCol + 2][aRow] = av.z;
        As[aCol + 3][aRow] = av.w;
        *reinterpret_cast<float4*>(&Bs[bRow][bCol]) =
            *reinterpret_cast<const float4*>(V + (size_t)(kt + bRow) * N + bx * 128 + bCol);
        __syncthreads();
        #pragma unroll
        for (int kk = 0; kk < 8; kk++) {
            const unsigned long long* Bs2 =
                reinterpret_cast<const unsigned long long*>(&Bs[kk][tx * 8]);
            unsigned long long rn[4];
            #pragma unroll
            for (int j = 0; j < 4; j++) rn[j] = Bs2[j];
            #pragma unroll
            for (int i = 0; i < 8; i++) {
                unsigned long long m2 = pack_dup(As[kk][ty * 8 + i]);
                #pragma unroll
                for (int j = 0; j < 4; j++) fma2(acc[i][j], m2, rn[j]);
            }
        }
        __syncthreads();
    }

    #pragma unroll
    for (int i = 0; i < 8; i++) {
        int row = by * 128 + ty * 8 + i;
        #pragma unroll
        for (int j = 0; j < 4; j++) {
            float2 v = *reinterpret_cast<float2*>(&acc[i][j]);
            int col = bx * 128 + tx * 8 + j * 2;
            *reinterpret_cast<float2*>(C + (size_t)row * N + col) = v;
        }
    }
}

// ---------------------------------------------------------------------------
extern "C" void kernel_launch(void* const* d_in, const int* in_sizes, int n_in,
                              void* d_out, int out_size) {
    const float* hs    = (const float*)d_in[0];   // [B,S,HID]
    const float* assoc = (const float*)d_in[1];   // [B,S,S]
    // d_in[2] = broad_hc_attn (unused: broad_heads == 0)
    const float* Wv    = (const float*)d_in[3];   // [HID, NH*HD]
    const float* bv    = (const float*)d_in[4];   // [NH*HD]
    float*       out   = (float*)d_out;           // [B,S,NH*HD]

    (void)in_sizes; (void)n_in; (void)out_size;

    rowsum_kernel<<<B_ * S_, 256>>>(assoc);
    sgemm_value<<<dim3(NHD_ / 128, (B_ * S_) / 128), 256>>>(hs, Wv, bv);
    sgemm_attn<<<dim3(NHD_ / 128, S_ / 128, B_), 256>>>(assoc, out);
}

// round 5
// speedup vs baseline: 2.3528x; 2.3528x over previous
#include <cuda_runtime.h>
#include <cuda_bf16.h>
#include <cstdint>

#define B_   4
#define S_   2048
#define HID_ 1024
#define NHD_ 1024
#define EPS_ 1e-6f

// ---------------------------------------------------------------------------
// Scratch (allocation-free rule: device globals only)  ~137 MB
// ---------------------------------------------------------------------------
__device__ __nv_bfloat16 g_hs_hi[(size_t)B_ * S_ * HID_];
__device__ __nv_bfloat16 g_hs_lo[(size_t)B_ * S_ * HID_];
__device__ __nv_bfloat16 g_wv_hi[(size_t)HID_ * NHD_];
__device__ __nv_bfloat16 g_wv_lo[(size_t)HID_ * NHD_];
__device__ __nv_bfloat16 g_at_hi[(size_t)B_ * S_ * S_];
__device__ __nv_bfloat16 g_at_lo[(size_t)B_ * S_ * S_];
__device__ __nv_bfloat16 g_v_hi[(size_t)B_ * S_ * NHD_];
__device__ __nv_bfloat16 g_v_lo[(size_t)B_ * S_ * NHD_];

// ---------------------------------------------------------------------------
// Helpers (all plain-sm_103-legal: cp.async / ldmatrix / mma.sync)
// ---------------------------------------------------------------------------
__device__ __forceinline__ uint32_t smem_u32(const void* p) {
    uint32_t a;
    asm("{ .reg .u64 t; cvta.to.shared.u64 t, %1; cvt.u32.u64 %0, t; }"
        : "=r"(a) : "l"(p));
    return a;
}
__device__ __forceinline__ void cp16(uint32_t dst, const void* src) {
    asm volatile("cp.async.cg.shared.global [%0], [%1], 16;"
                 :: "r"(dst), "l"(src) : "memory");
}
#define CP_COMMIT() asm volatile("cp.async.commit_group;" ::: "memory")
#define CP_WAIT2()  asm volatile("cp.async.wait_group 2;" ::: "memory")

__device__ __forceinline__ void ldsm_x4(uint32_t* r, uint32_t a) {
    asm volatile("ldmatrix.sync.aligned.m8n8.x4.shared.b16 {%0,%1,%2,%3}, [%4];"
                 : "=r"(r[0]), "=r"(r[1]), "=r"(r[2]), "=r"(r[3]) : "r"(a));
}
__device__ __forceinline__ void ldsm_x4_t(uint32_t* r, uint32_t a) {
    asm volatile("ldmatrix.sync.aligned.m8n8.x4.trans.shared.b16 {%0,%1,%2,%3}, [%4];"
                 : "=r"(r[0]), "=r"(r[1]), "=r"(r[2]), "=r"(r[3]) : "r"(a));
}
__device__ __forceinline__ void mma_bf16(float* c, const uint32_t* a, const uint32_t* b) {
    asm volatile(
        "mma.sync.aligned.m16n8k16.row.col.f32.bf16.bf16.f32 "
        "{%0,%1,%2,%3}, {%4,%5,%6,%7}, {%8,%9}, {%0,%1,%2,%3};"
        : "+f"(c[0]), "+f"(c[1]), "+f"(c[2]), "+f"(c[3])
        : "r"(a[0]), "r"(a[1]), "r"(a[2]), "r"(a[3]), "r"(b[0]), "r"(b[1]));
}

__device__ __forceinline__ void split2(float v, unsigned short& h, unsigned short& l) {
    __nv_bfloat16 hb = __float2bfloat16_rn(v);
    float r = v - __bfloat162float(hb);
    __nv_bfloat16 lb = __float2bfloat16_rn(r);
    h = __bfloat16_as_ushort(hb);
    l = __bfloat16_as_ushort(lb);
}

// ---------------------------------------------------------------------------
// Prep kernels
// ---------------------------------------------------------------------------
__global__ __launch_bounds__(256) void attn_prep(const float* __restrict__ attn) {
    int row = blockIdx.x;              // b*S + q
    int q   = row & (S_ - 1);
    const float* a = attn + (size_t)row * S_;
    float s = 0.f;
    for (int k = threadIdx.x; k <= q; k += 256) s += a[k];
    #pragma unroll
    for (int o = 16; o; o >>= 1) s += __shfl_down_sync(0xffffffffu, s, o);
    __shared__ float red[8];
    __shared__ float sinv;
    if ((threadIdx.x & 31) == 0) red[threadIdx.x >> 5] = s;
    __syncthreads();
    if (threadIdx.x == 0) {
        float t = 0.f;
        #pragma unroll
        for (int i = 0; i < 8; i++) t += red[i];
        sinv = 1.f / (EPS_ + t);
    }
    __syncthreads();
    float inv = sinv;
    ushort4* Hi = reinterpret_cast<ushort4*>(g_at_hi + (size_t)row * S_);
    ushort4* Lo = reinterpret_cast<ushort4*>(g_at_lo + (size_t)row * S_);
    for (int c = threadIdx.x; c < S_ / 4; c += 256) {
        int k = c * 4;
        float4 v = *reinterpret_cast<const float4*>(a + k);
        float f0 = (k + 0 <= q) ? v.x * inv : 0.f;
        float f1 = (k + 1 <= q) ? v.y * inv : 0.f;
        float f2 = (k + 2 <= q) ? v.z * inv : 0.f;
        float f3 = (k + 3 <= q) ? v.w * inv : 0.f;
        ushort4 H, L;
        split2(f0, H.x, L.x); split2(f1, H.y, L.y);
        split2(f2, H.z, L.z); split2(f3, H.w, L.w);
        Hi[c] = H; Lo[c] = L;
    }
}

__global__ __launch_bounds__(256) void split_array(const float* __restrict__ src,
                                                   __nv_bfloat16* __restrict__ dhi,
                                                   __nv_bfloat16* __restrict__ dlo) {
    size_t i = (size_t)blockIdx.x * 256 + threadIdx.x;   // float4 index
    float4 v = reinterpret_cast<const float4*>(src)[i];
    ushort4 H, L;
    split2(v.x, H.x, L.x); split2(v.y, H.y, L.y);
    split2(v.z, H.z, L.z); split2(v.w, H.w, L.w);
    reinterpret_cast<ushort4*>(dhi)[i] = H;
    reinterpret_cast<ushort4*>(dlo)[i] = L;
}

// ---------------------------------------------------------------------------
// HMMA GEMM: C[m,n] = sum_k A[m,k] * B[k,n]     (A,B pre-split bf16 hi/lo)
// 128x128 CTA tile, BK=32, 8 warps (64x32 each), 3-stage cp.async pipeline,
// 3-product bf16 emulation of fp32 into shared fp32 accumulators.
// Smem per stage: Ah[128][40] Al[128][40] Bh[32][136] Bl[32][136] = 37888 B
// ---------------------------------------------------------------------------
static constexpr int STG = 37888;
static constexpr int GEMM_SMEM = 3 * STG;   // 113664

template <bool CAUSAL, bool SPLIT_EPI>
__global__ __launch_bounds__(256) void mma_gemm(
    const __nv_bfloat16* __restrict__ Agh, const __nv_bfloat16* __restrict__ Agl,
    const __nv_bfloat16* __restrict__ Bgh, const __nv_bfloat16* __restrict__ Bgl,
    float* __restrict__ Cf, __nv_bfloat16* __restrict__ Chi,
    __nv_bfloat16* __restrict__ Clo, const float* __restrict__ bias,
    int K, int ldA, int ldB, int ldC,
    size_t strA, size_t strB, size_t strC) {
    extern __shared__ char dsm[];
    const uint32_t sbase = smem_u32(dsm);
    const int tid = threadIdx.x, lane = tid & 31, wid = tid >> 5;
    const int bx = blockIdx.x;
    const int by = CAUSAL ? (gridDim.y - 1 - blockIdx.y) : blockIdx.y;
    const int bz = blockIdx.z;
    const int m0 = by * 128, n0 = bx * 128;

    Agh += (size_t)bz * strA; Agl += (size_t)bz * strA;
    Bgh += (size_t)bz * strB; Bgl += (size_t)bz * strB;

    const int nk = CAUSAL ? (by + 1) * 4 : (K >> 5);

    // per-thread load coordinates
    const int ra  = tid >> 2,  ca8 = (tid & 3) * 8;    // A: 2 rows per thread
    const int rb  = tid >> 4,  cb8 = (tid & 15) * 8;   // B: 2 rows per thread

    auto load_stage = [&](int buf, int chunk) {
        const uint32_t st = sbase + buf * STG;
        const int k0 = chunk * 32;
        // A hi / lo  (rows ra, ra+64)
        cp16(st + ra * 80 + (tid & 3) * 16,
             Agh + (size_t)(m0 + ra) * ldA + k0 + ca8);
        cp16(st + (ra + 64) * 80 + (tid & 3) * 16,
             Agh + (size_t)(m0 + ra + 64) * ldA + k0 + ca8);
        cp16(st + 10240 + ra * 80 + (tid & 3) * 16,
             Agl + (size_t)(m0 + ra) * ldA + k0 + ca8);
        cp16(st + 10240 + (ra + 64) * 80 + (tid & 3) * 16,
             Agl + (size_t)(m0 + ra + 64) * ldA + k0 + ca8);
        // B hi / lo  (rows rb, rb+16)
        cp16(st + 20480 + rb * 272 + (tid & 15) * 16,
             Bgh + (size_t)(k0 + rb) * ldB + n0 + cb8);
        cp16(st + 20480 + (rb + 16) * 272 + (tid & 15) * 16,
             Bgh + (size_t)(k0 + rb + 16) * ldB + n0 + cb8);
        cp16(st + 29184 + rb * 272 + (tid & 15) * 16,
             Bgl + (size_t)(k0 + rb) * ldB + n0 + cb8);
        cp16(st + 29184 + (rb + 16) * 272 + (tid & 15) * 16,
             Bgl + (size_t)(k0 + rb + 16) * ldB + n0 + cb8);
    };

    float acc[4][4][4];
    #pragma unroll
    for (int i = 0; i < 4; i++)
        #pragma unroll
        for (int j = 0; j < 4; j++)
            #pragma unroll
            for (int t = 0; t < 4; t++) acc[i][j][t] = 0.f;

    const int wm = (wid >> 2) * 64;      // warp m-offset within CTA
    const int wn = (wid & 3) * 32;       // warp n-offset within CTA

    // prologue: stages 0,1
    load_stage(0, 0); CP_COMMIT();
    load_stage(1, 1); CP_COMMIT();

    int fetch = 2;
    for (int kt = 0; kt < nk; kt++) {
        if (fetch < nk) load_stage(fetch % 3, fetch);
        CP_COMMIT();
        fetch++;
        CP_WAIT2();
        __syncthreads();

        const uint32_t st = sbase + (kt % 3) * STG;
        #pragma unroll
        for (int kk = 0; kk < 2; kk++) {
            const int k16 = kk * 16;
            uint32_t a_h[4][4], a_l[4][4], b_h[4][2], b_l[4][2];
            #pragma unroll
            for (int mt = 0; mt < 4; mt++) {
                uint32_t off = ((wm + mt * 16 + (lane & 15)) * 80 +
                                (k16 + (lane >> 4) * 8) * 2);
                ldsm_x4(a_h[mt], st + off);
                ldsm_x4(a_l[mt], st + 10240 + off);
            }
            #pragma unroll
            for (int np = 0; np < 2; np++) {
                uint32_t off = ((k16 + (lane & 15)) * 272 +
                                (wn + np * 16 + (lane >> 4) * 8) * 2);
                uint32_t t4[4];
                ldsm_x4_t(t4, st + 20480 + off);
                b_h[np * 2][0] = t4[0]; b_h[np * 2][1] = t4[1];
                b_h[np * 2 + 1][0] = t4[2]; b_h[np * 2 + 1][1] = t4[3];
                ldsm_x4_t(t4, st + 29184 + off);
                b_l[np * 2][0] = t4[0]; b_l[np * 2][1] = t4[1];
                b_l[np * 2 + 1][0] = t4[2]; b_l[np * 2 + 1][1] = t4[3];
            }
            #pragma unroll
            for (int mt = 0; mt < 4; mt++)
                #pragma unroll
                for (int nt = 0; nt < 4; nt++) {
                    mma_bf16(acc[mt][nt], a_h[mt], b_h[nt]);
                    mma_bf16(acc[mt][nt], a_l[mt], b_h[nt]);
                    mma_bf16(acc[mt][nt], a_h[mt], b_l[nt]);
                }
        }
        __syncthreads();
    }

    // epilogue
    const int gr = lane >> 2, gc = (lane & 3) * 2;
    #pragma unroll
    for (int mt = 0; mt < 4; mt++) {
        const int mrow = m0 + wm + mt * 16 + gr;
        #pragma unroll
        for (int nt = 0; nt < 4; nt++) {
            const int ncol = n0 + wn + nt * 8 + gc;
            #pragma unroll
            for (int h = 0; h < 2; h++) {
                const int r = mrow + h * 8;
                float v0 = acc[mt][nt][h * 2 + 0];
                float v1 = acc[mt][nt][h * 2 + 1];
                if (SPLIT_EPI) {
                    const float2 bb = *reinterpret_cast<const float2*>(bias + ncol);
                    v0 += bb.x; v1 += bb.y;
                    unsigned short h0, l0, h1, l1;
                    split2(v0, h0, l0);
                    split2(v1, h1, l1);
                    uint32_t hp = (uint32_t)h0 | ((uint32_t)h1 << 16);
                    uint32_t lp = (uint32_t)l0 | ((uint32_t)l1 << 16);
                    *reinterpret_cast<uint32_t*>(Chi + (size_t)r * ldC + ncol) = hp;
                    *reinterpret_cast<uint32_t*>(Clo + (size_t)r * ldC + ncol) = lp;
                } else {
                    float2 o; o.x = v0; o.y = v1;
                    *reinterpret_cast<float2*>(Cf + (size_t)bz * strC +
                                               (size_t)r * ldC + ncol) = o;
                }
            }
        }
    }
}

// ---------------------------------------------------------------------------
extern "C" void kernel_launch(void* const* d_in, const int* in_sizes, int n_in,
                              void* d_out, int out_size) {
    const float* hs    = (const float*)d_in[0];   // [B,S,HID]
    const float* assoc = (const float*)d_in[1];   // [B,S,S]
    // d_in[2] = broad_hc_attn (unused: broad_heads == 0)
    const float* Wv    = (const float*)d_in[3];   // [HID, NH*HD]
    const float* bv    = (const float*)d_in[4];   // [NH*HD]
    float*       out   = (float*)d_out;           // [B,S,NH*HD]
    (void)in_sizes; (void)n_in; (void)out_size;

    cudaFuncSetAttribute(mma_gemm<false, true>,
                         cudaFuncAttributeMaxDynamicSharedMemorySize, GEMM_SMEM);
    cudaFuncSetAttribute(mma_gemm<true, false>,
                         cudaFuncAttributeMaxDynamicSharedMemorySize, GEMM_SMEM);

    __nv_bfloat16 *hs_hi, *hs_lo, *wv_hi, *wv_lo, *at_hi, *at_lo, *v_hi, *v_lo;
    cudaGetSymbolAddress((void**)&hs_hi, g_hs_hi);
    cudaGetSymbolAddress((void**)&hs_lo, g_hs_lo);
    cudaGetSymbolAddress((void**)&wv_hi, g_wv_hi);
    cudaGetSymbolAddress((void**)&wv_lo, g_wv_lo);
    cudaGetSymbolAddress((void**)&at_hi, g_at_hi);
    cudaGetSymbolAddress((void**)&at_lo, g_at_lo);
    cudaGetSymbolAddress((void**)&v_hi, g_v_hi);
    cudaGetSymbolAddress((void**)&v_lo, g_v_lo);

    // 1. attn: rowsum + normalize + causal mask + bf16 hi/lo split
    attn_prep<<<B_ * S_, 256>>>(assoc);
    // 2. hidden_states hi/lo split
    split_array<<<(int)(((size_t)B_ * S_ * HID_ / 4) / 256), 256>>>(hs, hs_hi, hs_lo);
    // 3. Wv hi/lo split (row-major [K][N] — consumed directly via ldmatrix.trans)
    split_array<<<(int)(((size_t)HID_ * NHD_ / 4) / 256), 256>>>(Wv, wv_hi, wv_lo);
    // 4. value = hs @ Wv + bv  -> split hi/lo in epilogue (GEMM2's B operand)
    mma_gemm<false, true><<<dim3(NHD_ / 128, (B_ * S_) / 128, 1), 256, GEMM_SMEM>>>(
        hs_hi, hs_lo, wv_hi, wv_lo, nullptr, v_hi, v_lo, bv,
        HID_, HID_, NHD_, NHD_, 0, 0, 0);
    // 5. out = norm_causal(attn) @ value   (causal k-truncation, heavy blocks first)
    mma_gemm<true, false><<<dim3(NHD_ / 128, S_ / 128, B_), 256, GEMM_SMEM>>>(
        at_hi, at_lo, v_hi, v_lo, out, nullptr, nullptr, nullptr,
        S_, S_, NHD_, NHD_,
        (size_t)S_ * S_, (size_t)S_ * NHD_, (size_t)S_ * NHD_);
}

// round 7
// speedup vs baseline: 3.4326x; 1.4589x over previous
#include <cuda_runtime.h>
#include <cuda_bf16.h>
#include <cstdint>

#define B_   4
#define S_   2048
#define HID_ 1024
#define NHD_ 1024
#define EPS_ 1e-6f

// ---------------------------------------------------------------------------
// Scratch (allocation-free rule: device globals only)  ~137 MB
// ---------------------------------------------------------------------------
__device__ __nv_bfloat16 g_hs_hi[(size_t)B_ * S_ * HID_];
__device__ __nv_bfloat16 g_hs_lo[(size_t)B_ * S_ * HID_];
__device__ __nv_bfloat16 g_wv_hi[(size_t)HID_ * NHD_];
__device__ __nv_bfloat16 g_wv_lo[(size_t)HID_ * NHD_];
__device__ __nv_bfloat16 g_at_hi[(size_t)B_ * S_ * S_];
__device__ __nv_bfloat16 g_at_lo[(size_t)B_ * S_ * S_];
__device__ __nv_bfloat16 g_v_hi[(size_t)B_ * S_ * NHD_];
__device__ __nv_bfloat16 g_v_lo[(size_t)B_ * S_ * NHD_];

// ---------------------------------------------------------------------------
// Helpers (all plain-sm_103-legal: cp.async / ldmatrix / mma.sync)
// ---------------------------------------------------------------------------
__device__ __forceinline__ uint32_t smem_u32(const void* p) {
    uint32_t a;
    asm("{ .reg .u64 t; cvta.to.shared.u64 t, %1; cvt.u32.u64 %0, t; }"
        : "=r"(a) : "l"(p));
    return a;
}
__device__ __forceinline__ void cp16(uint32_t dst, const void* src) {
    asm volatile("cp.async.cg.shared.global [%0], [%1], 16;"
                 :: "r"(dst), "l"(src) : "memory");
}
#define CP_COMMIT() asm volatile("cp.async.commit_group;" ::: "memory")
#define CP_WAIT1()  asm volatile("cp.async.wait_group 1;" ::: "memory")

__device__ __forceinline__ void ldsm_x4(uint32_t* r, uint32_t a) {
    asm volatile("ldmatrix.sync.aligned.m8n8.x4.shared.b16 {%0,%1,%2,%3}, [%4];"
                 : "=r"(r[0]), "=r"(r[1]), "=r"(r[2]), "=r"(r[3]) : "r"(a));
}
__device__ __forceinline__ void ldsm_x4_t(uint32_t* r, uint32_t a) {
    asm volatile("ldmatrix.sync.aligned.m8n8.x4.trans.shared.b16 {%0,%1,%2,%3}, [%4];"
                 : "=r"(r[0]), "=r"(r[1]), "=r"(r[2]), "=r"(r[3]) : "r"(a));
}
__device__ __forceinline__ void mma_bf16(float* c, const uint32_t* a, const uint32_t* b) {
    asm volatile(
        "mma.sync.aligned.m16n8k16.row.col.f32.bf16.bf16.f32 "
        "{%0,%1,%2,%3}, {%4,%5,%6,%7}, {%8,%9}, {%0,%1,%2,%3};"
        : "+f"(c[0]), "+f"(c[1]), "+f"(c[2]), "+f"(c[3])
        : "r"(a[0]), "r"(a[1]), "r"(a[2]), "r"(a[3]), "r"(b[0]), "r"(b[1]));
}

__device__ __forceinline__ void split2(float v, unsigned short& h, unsigned short& l) {
    __nv_bfloat16 hb = __float2bfloat16_rn(v);
    float r = v - __bfloat162float(hb);
    __nv_bfloat16 lb = __float2bfloat16_rn(r);
    h = __bfloat16_as_ushort(hb);
    l = __bfloat16_as_ushort(lb);
}

// ---------------------------------------------------------------------------
// Prep kernels
// ---------------------------------------------------------------------------
__global__ __launch_bounds__(256) void attn_prep(const float* __restrict__ attn) {
    int row = blockIdx.x;              // b*S + q
    int q   = row & (S_ - 1);
    const float* a = attn + (size_t)row * S_;
    float s = 0.f;
    for (int k = threadIdx.x; k <= q; k += 256) s += a[k];
    #pragma unroll
    for (int o = 16; o; o >>= 1) s += __shfl_down_sync(0xffffffffu, s, o);
    __shared__ float red[8];
    __shared__ float sinv;
    if ((threadIdx.x & 31) == 0) red[threadIdx.x >> 5] = s;
    __syncthreads();
    if (threadIdx.x == 0) {
        float t = 0.f;
        #pragma unroll
        for (int i = 0; i < 8; i++) t += red[i];
        sinv = 1.f / (EPS_ + t);
    }
    __syncthreads();
    float inv = sinv;
    ushort4* Hi = reinterpret_cast<ushort4*>(g_at_hi + (size_t)row * S_);
    ushort4* Lo = reinterpret_cast<ushort4*>(g_at_lo + (size_t)row * S_);
    for (int c = threadIdx.x; c < S_ / 4; c += 256) {
        int k = c * 4;
        float4 v = *reinterpret_cast<const float4*>(a + k);
        float f0 = (k + 0 <= q) ? v.x * inv : 0.f;
        float f1 = (k + 1 <= q) ? v.y * inv : 0.f;
        float f2 = (k + 2 <= q) ? v.z * inv : 0.f;
        float f3 = (k + 3 <= q) ? v.w * inv : 0.f;
        ushort4 H, L;
        split2(f0, H.x, L.x); split2(f1, H.y, L.y);
        split2(f2, H.z, L.z); split2(f3, H.w, L.w);
        Hi[c] = H; Lo[c] = L;
    }
}

__global__ __launch_bounds__(256) void split_array(const float* __restrict__ src,
                                                   __nv_bfloat16* __restrict__ dhi,
                                                   __nv_bfloat16* __restrict__ dlo) {
    size_t i = (size_t)blockIdx.x * 256 + threadIdx.x;   // float4 index
    float4 v = reinterpret_cast<const float4*>(src)[i];
    ushort4 H, L;
    split2(v.x, H.x, L.x); split2(v.y, H.y, L.y);
    split2(v.z, H.z, L.z); split2(v.w, H.w, L.w);
    reinterpret_cast<ushort4*>(dhi)[i] = H;
    reinterpret_cast<ushort4*>(dlo)[i] = L;
}

// ---------------------------------------------------------------------------
// HMMA GEMM: C[m,n] = sum_k A[m,k] * B[k,n]     (A,B pre-split bf16 hi/lo)
// 128x128 CTA tile, BK=32, 8 warps (64x32 each), 2-stage cp.async pipeline,
// 2 CTAs/SM co-residency, 3-product bf16 emulation of fp32.
// Smem per stage: Ah[128][40] Al[128][40] Bh[32][136] Bl[32][136] = 37888 B
// ---------------------------------------------------------------------------
static constexpr int STG = 37888;
static constexpr int GEMM_SMEM = 2 * STG;   // 75776  (x2 CTAs = 151552 <= 228KB)

template <bool CAUSAL, bool SPLIT_EPI>
__global__ __launch_bounds__(256, 2) void mma_gemm(
    const __nv_bfloat16* __restrict__ Agh, const __nv_bfloat16* __restrict__ Agl,
    const __nv_bfloat16* __restrict__ Bgh, const __nv_bfloat16* __restrict__ Bgl,
    float* __restrict__ Cf, __nv_bfloat16* __restrict__ Chi,
    __nv_bfloat16* __restrict__ Clo, const float* __restrict__ bias,
    int K, int ldA, int ldB, int ldC,
    size_t strA, size_t strB, size_t strC) {
    extern __shared__ char dsm[];
    const uint32_t sbase = smem_u32(dsm);
    const int tid = threadIdx.x, lane = tid & 31, wid = tid >> 5;
    const int bx = blockIdx.x;
    const int by = CAUSAL ? (gridDim.y - 1 - blockIdx.y) : blockIdx.y;
    const int bz = blockIdx.z;
    const int m0 = by * 128, n0 = bx * 128;

    Agh += (size_t)bz * strA; Agl += (size_t)bz * strA;
    Bgh += (size_t)bz * strB; Bgl += (size_t)bz * strB;

    const int nk = CAUSAL ? (by + 1) * 4 : (K >> 5);

    // per-thread load coordinates
    const int ra  = tid >> 2,  ca8 = (tid & 3) * 8;    // A: 2 rows per thread
    const int rb  = tid >> 4,  cb8 = (tid & 15) * 8;   // B: 2 rows per thread

    auto load_stage = [&](int buf, int chunk) {
        const uint32_t st = sbase + buf * STG;
        const int k0 = chunk * 32;
        // A hi / lo  (rows ra, ra+64)
        cp16(st + ra * 80 + (tid & 3) * 16,
             Agh + (size_t)(m0 + ra) * ldA + k0 + ca8);
        cp16(st + (ra + 64) * 80 + (tid & 3) * 16,
             Agh + (size_t)(m0 + ra + 64) * ldA + k0 + ca8);
        cp16(st + 10240 + ra * 80 + (tid & 3) * 16,
             Agl + (size_t)(m0 + ra) * ldA + k0 + ca8);
        cp16(st + 10240 + (ra + 64) * 80 + (tid & 3) * 16,
             Agl + (size_t)(m0 + ra + 64) * ldA + k0 + ca8);
        // B hi / lo  (rows rb, rb+16)
        cp16(st + 20480 + rb * 272 + (tid & 15) * 16,
             Bgh + (size_t)(k0 + rb) * ldB + n0 + cb8);
        cp16(st + 20480 + (rb + 16) * 272 + (tid & 15) * 16,
             Bgh + (size_t)(k0 + rb + 16) * ldB + n0 + cb8);
        cp16(st + 29184 + rb * 272 + (tid & 15) * 16,
             Bgl + (size_t)(k0 + rb) * ldB + n0 + cb8);
        cp16(st + 29184 + (rb + 16) * 272 + (tid & 15) * 16,
             Bgl + (size_t)(k0 + rb + 16) * ldB + n0 + cb8);
    };

    float acc[4][4][4];
    #pragma unroll
    for (int i = 0; i < 4; i++)
        #pragma unroll
        for (int j = 0; j < 4; j++)
            #pragma unroll
            for (int t = 0; t < 4; t++) acc[i][j][t] = 0.f;

    const int wm = (wid >> 2) * 64;      // warp m-offset within CTA
    const int wn = (wid & 3) * 32;       // warp n-offset within CTA

    // prologue: both stages
    load_stage(0, 0); CP_COMMIT();
    if (nk > 1) load_stage(1, 1);
    CP_COMMIT();

    for (int kt = 0; kt < nk; kt++) {
        CP_WAIT1();                 // stage kt%2 complete (<=1 group pending)
        __syncthreads();

        const uint32_t st = sbase + (kt & 1) * STG;
        #pragma unroll
        for (int kk = 0; kk < 2; kk++) {
            const int k16 = kk * 16;
            uint32_t a_h[4][4], a_l[4][4], b_h[4][2], b_l[4][2];
            #pragma unroll
            for (int mt = 0; mt < 4; mt++) {
                uint32_t off = ((wm + mt * 16 + (lane & 15)) * 80 +
                                (k16 + (lane >> 4) * 8) * 2);
                ldsm_x4(a_h[mt], st + off);
                ldsm_x4(a_l[mt], st + 10240 + off);
            }
            #pragma unroll
            for (int np = 0; np < 2; np++) {
                uint32_t off = ((k16 + (lane & 15)) * 272 +
                                (wn + np * 16 + (lane >> 4) * 8) * 2);
                uint32_t t4[4];
                ldsm_x4_t(t4, st + 20480 + off);
                b_h[np * 2][0] = t4[0]; b_h[np * 2][1] = t4[1];
                b_h[np * 2 + 1][0] = t4[2]; b_h[np * 2 + 1][1] = t4[3];
                ldsm_x4_t(t4, st + 29184 + off);
                b_l[np * 2][0] = t4[0]; b_l[np * 2][1] = t4[1];
                b_l[np * 2 + 1][0] = t4[2]; b_l[np * 2 + 1][1] = t4[3];
            }
            #pragma unroll
            for (int mt = 0; mt < 4; mt++)
                #pragma unroll
                for (int nt = 0; nt < 4; nt++) {
                    mma_bf16(acc[mt][nt], a_h[mt], b_h[nt]);
                    mma_bf16(acc[mt][nt], a_l[mt], b_h[nt]);
                    mma_bf16(acc[mt][nt], a_h[mt], b_l[nt]);
                }
        }
        __syncthreads();            // stage kt%2 fully consumed
        if (kt + 2 < nk) load_stage(kt & 1, kt + 2);
        CP_COMMIT();                // always commit (possibly empty group)
    }

    // epilogue
    const int gr = lane >> 2, gc = (lane & 3) * 2;
    #pragma unroll
    for (int mt = 0; mt < 4; mt++) {
        const int mrow = m0 + wm + mt * 16 + gr;
        #pragma unroll
        for (int nt = 0; nt < 4; nt++) {
            const int ncol = n0 + wn + nt * 8 + gc;
            #pragma unroll
            for (int h = 0; h < 2; h++) {
                const int r = mrow + h * 8;
                float v0 = acc[mt][nt][h * 2 + 0];
                float v1 = acc[mt][nt][h * 2 + 1];
                if (SPLIT_EPI) {
                    const float2 bb = *reinterpret_cast<const float2*>(bias + ncol);
                    v0 += bb.x; v1 += bb.y;
                    unsigned short h0, l0, h1, l1;
                    split2(v0, h0, l0);
                    split2(v1, h1, l1);
                    uint32_t hp = (uint32_t)h0 | ((uint32_t)h1 << 16);
                    uint32_t lp = (uint32_t)l0 | ((uint32_t)l1 << 16);
                    *reinterpret_cast<uint32_t*>(Chi + (size_t)r * ldC + ncol) = hp;
                    *reinterpret_cast<uint32_t*>(Clo + (size_t)r * ldC + ncol) = lp;
                } else {
                    float2 o; o.x = v0; o.y = v1;
                    *reinterpret_cast<float2*>(Cf + (size_t)bz * strC +
                                               (size_t)r * ldC + ncol) = o;
                }
            }
        }
    }
}

// ---------------------------------------------------------------------------
extern "C" void kernel_launch(void* const* d_in, const int* in_sizes, int n_in,
                              void* d_out, int out_size) {
    const float* hs    = (const float*)d_in[0];   // [B,S,HID]
    const float* assoc = (const float*)d_in[1];   // [B,S,S]
    // d_in[2] = broad_hc_attn (unused: broad_heads == 0)
    const float* Wv    = (const float*)d_in[3];   // [HID, NH*HD]
    const float* bv    = (const float*)d_in[4];   // [NH*HD]
    float*       out   = (float*)d_out;           // [B,S,NH*HD]
    (void)in_sizes; (void)n_in; (void)out_size;

    cudaFuncSetAttribute(mma_gemm<false, true>,
                         cudaFuncAttributeMaxDynamicSharedMemorySize, GEMM_SMEM);
    cudaFuncSetAttribute(mma_gemm<true, false>,
                         cudaFuncAttributeMaxDynamicSharedMemorySize, GEMM_SMEM);

    __nv_bfloat16 *hs_hi, *hs_lo, *wv_hi, *wv_lo, *at_hi, *at_lo, *v_hi, *v_lo;
    cudaGetSymbolAddress((void**)&hs_hi, g_hs_hi);
    cudaGetSymbolAddress((void**)&hs_lo, g_hs_lo);
    cudaGetSymbolAddress((void**)&wv_hi, g_wv_hi);
    cudaGetSymbolAddress((void**)&wv_lo, g_wv_lo);
    cudaGetSymbolAddress((void**)&at_hi, g_at_hi);
    cudaGetSymbolAddress((void**)&at_lo, g_at_lo);
    cudaGetSymbolAddress((void**)&v_hi, g_v_hi);
    cudaGetSymbolAddress((void**)&v_lo, g_v_lo);

    // 1. attn: rowsum + normalize + causal mask + bf16 hi/lo split
    attn_prep<<<B_ * S_, 256>>>(assoc);
    // 2. hidden_states hi/lo split
    split_array<<<(int)(((size_t)B_ * S_ * HID_ / 4) / 256), 256>>>(hs, hs_hi, hs_lo);
    // 3. Wv hi/lo split (row-major [K][N] — consumed directly via ldmatrix.trans)
    split_array<<<(int)(((size_t)HID_ * NHD_ / 4) / 256), 256>>>(Wv, wv_hi, wv_lo);
    // 4. value = hs @ Wv + bv  -> split hi/lo in epilogue (GEMM2's B operand)
    mma_gemm<false, true><<<dim3(NHD_ / 128, (B_ * S_) / 128, 1), 256, GEMM_SMEM>>>(
        hs_hi, hs_lo, wv_hi, wv_lo, nullptr, v_hi, v_lo, bv,
        HID_, HID_, NHD_, NHD_, 0, 0, 0);
    // 5. out = norm_causal(attn) @ value   (causal k-truncation, heavy blocks first)
    mma_gemm<true, false><<<dim3(NHD_ / 128, S_ / 128, B_), 256, GEMM_SMEM>>>(
        at_hi, at_lo, v_hi, v_lo, out, nullptr, nullptr, nullptr,
        S_, S_, NHD_, NHD_,
        (size_t)S_ * S_, (size_t)S_ * NHD_, (size_t)S_ * NHD_);
}

// round 8
// speedup vs baseline: 4.6655x; 1.3592x over previous
#include <cuda_runtime.h>
#include <cuda_fp16.h>
#include <cstdint>

#define B_   4
#define S_   2048
#define HID_ 1024
#define NHD_ 1024
#define EPS_ 1e-6f

// ---------------------------------------------------------------------------
// Scratch (allocation-free rule: device globals only)  ~88 MB
// ---------------------------------------------------------------------------
__device__ __half g_hs_h[(size_t)B_ * S_ * HID_];
__device__ __half g_wv_h[(size_t)HID_ * NHD_];
__device__ __half g_wv_l[(size_t)HID_ * NHD_];
__device__ __half g_at_h[(size_t)B_ * S_ * S_];
__device__ __half g_v_h[(size_t)B_ * S_ * NHD_];
__device__ __half g_v_l[(size_t)B_ * S_ * NHD_];

// ---------------------------------------------------------------------------
// Helpers (plain-sm_103-legal: cp.async / ldmatrix / mma.sync)
// ---------------------------------------------------------------------------
__device__ __forceinline__ uint32_t smem_u32(const void* p) {
    uint32_t a;
    asm("{ .reg .u64 t; cvta.to.shared.u64 t, %1; cvt.u32.u64 %0, t; }"
        : "=r"(a) : "l"(p));
    return a;
}
__device__ __forceinline__ void cp16(uint32_t dst, const void* src) {
    asm volatile("cp.async.cg.shared.global [%0], [%1], 16;"
                 :: "r"(dst), "l"(src) : "memory");
}
#define CP_COMMIT() asm volatile("cp.async.commit_group;" ::: "memory")
#define CP_WAIT2()  asm volatile("cp.async.wait_group 2;" ::: "memory")

__device__ __forceinline__ void ldsm_x4(uint32_t* r, uint32_t a) {
    asm volatile("ldmatrix.sync.aligned.m8n8.x4.shared.b16 {%0,%1,%2,%3}, [%4];"
                 : "=r"(r[0]), "=r"(r[1]), "=r"(r[2]), "=r"(r[3]) : "r"(a));
}
__device__ __forceinline__ void ldsm_x4_t(uint32_t* r, uint32_t a) {
    asm volatile("ldmatrix.sync.aligned.m8n8.x4.trans.shared.b16 {%0,%1,%2,%3}, [%4];"
                 : "=r"(r[0]), "=r"(r[1]), "=r"(r[2]), "=r"(r[3]) : "r"(a));
}
__device__ __forceinline__ void mma_f16(float* c, const uint32_t* a, const uint32_t* b) {
    asm volatile(
        "mma.sync.aligned.m16n8k16.row.col.f32.f16.f16.f32 "
        "{%0,%1,%2,%3}, {%4,%5,%6,%7}, {%8,%9}, {%0,%1,%2,%3};"
        : "+f"(c[0]), "+f"(c[1]), "+f"(c[2]), "+f"(c[3])
        : "r"(a[0]), "r"(a[1]), "r"(a[2]), "r"(a[3]), "r"(b[0]), "r"(b[1]));
}

__device__ __forceinline__ void split2h(float v, unsigned short& h, unsigned short& l) {
    __half hb = __float2half_rn(v);
    float r = v - __half2float(hb);
    __half lb = __float2half_rn(r);
    h = __half_as_ushort(hb);
    l = __half_as_ushort(lb);
}

// ---------------------------------------------------------------------------
// Prep kernels
// ---------------------------------------------------------------------------
__global__ __launch_bounds__(256) void attn_prep(const float* __restrict__ attn) {
    int row = blockIdx.x;              // b*S + q
    int q   = row & (S_ - 1);
    const float* a = attn + (size_t)row * S_;
    float s = 0.f;
    for (int k = threadIdx.x; k <= q; k += 256) s += a[k];
    #pragma unroll
    for (int o = 16; o; o >>= 1) s += __shfl_down_sync(0xffffffffu, s, o);
    __shared__ float red[8];
    __shared__ float sinv;
    if ((threadIdx.x & 31) == 0) red[threadIdx.x >> 5] = s;
    __syncthreads();
    if (threadIdx.x == 0) {
        float t = 0.f;
        #pragma unroll
        for (int i = 0; i < 8; i++) t += red[i];
        sinv = 1.f / (EPS_ + t);
    }
    __syncthreads();
    float inv = sinv;
    ushort4* H = reinterpret_cast<ushort4*>(g_at_h + (size_t)row * S_);
    for (int c = threadIdx.x; c < S_ / 4; c += 256) {
        int k = c * 4;
        float4 v = *reinterpret_cast<const float4*>(a + k);
        ushort4 o;
        o.x = __half_as_ushort(__float2half_rn((k + 0 <= q) ? v.x * inv : 0.f));
        o.y = __half_as_ushort(__float2half_rn((k + 1 <= q) ? v.y * inv : 0.f));
        o.z = __half_as_ushort(__float2half_rn((k + 2 <= q) ? v.z * inv : 0.f));
        o.w = __half_as_ushort(__float2half_rn((k + 3 <= q) ? v.w * inv : 0.f));
        H[c] = o;
    }
}

__global__ __launch_bounds__(256) void split_hi(const float* __restrict__ src,
                                                __half* __restrict__ dh) {
    size_t i = (size_t)blockIdx.x * 256 + threadIdx.x;   // float4 index
    float4 v = reinterpret_cast<const float4*>(src)[i];
    ushort4 H;
    H.x = __half_as_ushort(__float2half_rn(v.x));
    H.y = __half_as_ushort(__float2half_rn(v.y));
    H.z = __half_as_ushort(__float2half_rn(v.z));
    H.w = __half_as_ushort(__float2half_rn(v.w));
    reinterpret_cast<ushort4*>(dh)[i] = H;
}

__global__ __launch_bounds__(256) void split_hilo(const float* __restrict__ src,
                                                  __half* __restrict__ dh,
                                                  __half* __restrict__ dl) {
    size_t i = (size_t)blockIdx.x * 256 + threadIdx.x;   // float4 index
    float4 v = reinterpret_cast<const float4*>(src)[i];
    ushort4 H, L;
    split2h(v.x, H.x, L.x); split2h(v.y, H.y, L.y);
    split2h(v.z, H.z, L.z); split2h(v.w, H.w, L.w);
    reinterpret_cast<ushort4*>(dh)[i] = H;
    reinterpret_cast<ushort4*>(dl)[i] = L;
}

// ---------------------------------------------------------------------------
// HMMA GEMM: C[m,n] = sum_k A[m,k] * B[k,n]
// A: fp16 hi-only.  B: fp16 hi+lo (2-product emulation: Ah@Bh + Ah@Bl).
// 128x128 CTA tile, BK=32, 8 warps (64x32 each), 3-stage cp.async pipeline,
// 2 CTAs/SM co-residency.
// Smem per stage: Ah[128][80B] Bh[32][272B] Bl[32][272B] = 27648 B
// ---------------------------------------------------------------------------
static constexpr int STG = 27648;
static constexpr int GEMM_SMEM = 3 * STG;   // 82944  (x2 CTAs = 165888 <= 228KB)
static constexpr int OFF_BH = 10240;
static constexpr int OFF_BL = 18944;

template <bool CAUSAL, bool SPLIT_EPI>
__global__ __launch_bounds__(256, 2) void mma_gemm(
    const __half* __restrict__ Ag,
    const __half* __restrict__ Bgh, const __half* __restrict__ Bgl,
    float* __restrict__ Cf, __half* __restrict__ Chi, __half* __restrict__ Clo,
    const float* __restrict__ bias,
    int K, int ldA, int ldB, int ldC,
    size_t strA, size_t strB, size_t strC) {
    extern __shared__ char dsm[];
    const uint32_t sbase = smem_u32(dsm);
    const int tid = threadIdx.x, lane = tid & 31, wid = tid >> 5;
    const int bx = blockIdx.x;
    const int by = CAUSAL ? (gridDim.y - 1 - blockIdx.y) : blockIdx.y;
    const int bz = blockIdx.z;
    const int m0 = by * 128, n0 = bx * 128;

    Ag  += (size_t)bz * strA;
    Bgh += (size_t)bz * strB;
    Bgl += (size_t)bz * strB;

    const int nk = CAUSAL ? (by + 1) * 4 : (K >> 5);

    auto load_stage = [&](int buf, int chunk) {
        const uint32_t st = sbase + buf * STG;
        const int k0 = chunk * 32;
        // A hi: 128 rows x 64B, 512 x 16B chunks, 2 per thread
        #pragma unroll
        for (int i = 0; i < 2; i++) {
            const int j = tid + 256 * i;
            const int row = j >> 2, c = j & 3;
            cp16(st + row * 80 + c * 16,
                 Ag + (size_t)(m0 + row) * ldA + k0 + c * 8);
        }
        // B hi / lo: 32 rows x 256B, 512 x 16B chunks each, 2 per thread
        #pragma unroll
        for (int i = 0; i < 2; i++) {
            const int j = tid + 256 * i;
            const int row = j >> 4, c = j & 15;
            cp16(st + OFF_BH + row * 272 + c * 16,
                 Bgh + (size_t)(k0 + row) * ldB + n0 + c * 8);
            cp16(st + OFF_BL + row * 272 + c * 16,
                 Bgl + (size_t)(k0 + row) * ldB + n0 + c * 8);
        }
    };

    float acc[4][4][4];
    #pragma unroll
    for (int i = 0; i < 4; i++)
        #pragma unroll
        for (int j = 0; j < 4; j++)
            #pragma unroll
            for (int t = 0; t < 4; t++) acc[i][j][t] = 0.f;

    const int wm = (wid >> 2) * 64;      // warp m-offset within CTA
    const int wn = (wid & 3) * 32;       // warp n-offset within CTA

    // prologue: stages 0,1
    load_stage(0, 0); CP_COMMIT();
    if (nk > 1) load_stage(1, 1);
    CP_COMMIT();

    int fetch = 2;
    for (int kt = 0; kt < nk; kt++) {
        if (fetch < nk) load_stage(fetch % 3, fetch);
        CP_COMMIT();
        fetch++;
        CP_WAIT2();
        __syncthreads();

        const uint32_t st = sbase + (kt % 3) * STG;
        #pragma unroll
        for (int kk = 0; kk < 2; kk++) {
            const int k16 = kk * 16;
            uint32_t a_r[4][4], b_h[4][2], b_l[4][2];
            #pragma unroll
            for (int mt = 0; mt < 4; mt++) {
                uint32_t off = ((wm + mt * 16 + (lane & 15)) * 80 +
                                (k16 + (lane >> 4) * 8) * 2);
                ldsm_x4(a_r[mt], st + off);
            }
            #pragma unroll
            for (int np = 0; np < 2; np++) {
                uint32_t off = ((k16 + (lane & 15)) * 272 +
                                (wn + np * 16 + (lane >> 4) * 8) * 2);
                uint32_t t4[4];
                ldsm_x4_t(t4, st + OFF_BH + off);
                b_h[np * 2][0] = t4[0]; b_h[np * 2][1] = t4[1];
                b_h[np * 2 + 1][0] = t4[2]; b_h[np * 2 + 1][1] = t4[3];
                ldsm_x4_t(t4, st + OFF_BL + off);
                b_l[np * 2][0] = t4[0]; b_l[np * 2][1] = t4[1];
                b_l[np * 2 + 1][0] = t4[2]; b_l[np * 2 + 1][1] = t4[3];
            }
            #pragma unroll
            for (int mt = 0; mt < 4; mt++)
                #pragma unroll
                for (int nt = 0; nt < 4; nt++) {
                    mma_f16(acc[mt][nt], a_r[mt], b_h[nt]);
                    mma_f16(acc[mt][nt], a_r[mt], b_l[nt]);
                }
        }
        __syncthreads();            // stage fully consumed before reuse
    }

    // epilogue
    const int gr = lane >> 2, gc = (lane & 3) * 2;
    #pragma unroll
    for (int mt = 0; mt < 4; mt++) {
        const int mrow = m0 + wm + mt * 16 + gr;
        #pragma unroll
        for (int nt = 0; nt < 4; nt++) {
            const int ncol = n0 + wn + nt * 8 + gc;
            #pragma unroll
            for (int h = 0; h < 2; h++) {
                const int r = mrow + h * 8;
                float v0 = acc[mt][nt][h * 2 + 0];
                float v1 = acc[mt][nt][h * 2 + 1];
                if (SPLIT_EPI) {
                    const float2 bb = *reinterpret_cast<const float2*>(bias + ncol);
                    v0 += bb.x; v1 += bb.y;
                    unsigned short h0, l0, h1, l1;
                    split2h(v0, h0, l0);
                    split2h(v1, h1, l1);
                    uint32_t hp = (uint32_t)h0 | ((uint32_t)h1 << 16);
                    uint32_t lp = (uint32_t)l0 | ((uint32_t)l1 << 16);
                    *reinterpret_cast<uint32_t*>(Chi + (size_t)r * ldC + ncol) = hp;
                    *reinterpret_cast<uint32_t*>(Clo + (size_t)r * ldC + ncol) = lp;
                } else {
                    float2 o; o.x = v0; o.y = v1;
                    *reinterpret_cast<float2*>(Cf + (size_t)bz * strC +
                                               (size_t)r * ldC + ncol) = o;
                }
            }
        }
    }
}

// ---------------------------------------------------------------------------
extern "C" void kernel_launch(void* const* d_in, const int* in_sizes, int n_in,
                              void* d_out, int out_size) {
    const float* hs    = (const float*)d_in[0];   // [B,S,HID]
    const float* assoc = (const float*)d_in[1];   // [B,S,S]
    // d_in[2] = broad_hc_attn (unused: broad_heads == 0)
    const float* Wv    = (const float*)d_in[3];   // [HID, NH*HD]
    const float* bv    = (const float*)d_in[4];   // [NH*HD]
    float*       out   = (float*)d_out;           // [B,S,NH*HD]
    (void)in_sizes; (void)n_in; (void)out_size;

    // one-time side stream + events for fork-join overlap (no device memory)
    static cudaStream_t s2 = nullptr;
    static cudaEvent_t ev1 = nullptr, ev2 = nullptr;
    if (s2 == nullptr) {
        cudaStreamCreateWithFlags(&s2, cudaStreamNonBlocking);
        cudaEventCreateWithFlags(&ev1, cudaEventDisableTiming);
        cudaEventCreateWithFlags(&ev2, cudaEventDisableTiming);
    }

    cudaFuncSetAttribute(mma_gemm<false, true>,
                         cudaFuncAttributeMaxDynamicSharedMemorySize, GEMM_SMEM);
    cudaFuncSetAttribute(mma_gemm<true, false>,
                         cudaFuncAttributeMaxDynamicSharedMemorySize, GEMM_SMEM);

    __half *hs_h, *wv_h, *wv_l, *at_h, *v_h, *v_l;
    cudaGetSymbolAddress((void**)&hs_h, g_hs_h);
    cudaGetSymbolAddress((void**)&wv_h, g_wv_h);
    cudaGetSymbolAddress((void**)&wv_l, g_wv_l);
    cudaGetSymbolAddress((void**)&at_h, g_at_h);
    cudaGetSymbolAddress((void**)&v_h, g_v_h);
    cudaGetSymbolAddress((void**)&v_l, g_v_l);

    // fork: attn prep (rowsum + normalize + mask + fp16) on side stream,
    // overlapped with the GEMM1 dependency chain on the main stream.
    cudaEventRecord(ev1, 0);
    cudaStreamWaitEvent(s2, ev1, 0);
    attn_prep<<<B_ * S_, 256, 0, s2>>>(assoc);
    cudaEventRecord(ev2, s2);

    // main stream: hs hi-split, Wv hi/lo split, GEMM1
    split_hi<<<(int)(((size_t)B_ * S_ * HID_ / 4) / 256), 256>>>(hs, hs_h);
    split_hilo<<<(int)(((size_t)HID_ * NHD_ / 4) / 256), 256>>>(Wv, wv_h, wv_l);
    mma_gemm<false, true><<<dim3(NHD_ / 128, (B_ * S_) / 128, 1), 256, GEMM_SMEM>>>(
        hs_h, wv_h, wv_l, nullptr, v_h, v_l, bv,
        HID_, HID_, NHD_, NHD_, 0, 0, 0);

    // join, then GEMM2 (causal k-truncation, heavy blocks first)
    cudaStreamWaitEvent(0, ev2, 0);
    mma_gemm<true, false><<<dim3(NHD_ / 128, S_ / 128, B_), 256, GEMM_SMEM>>>(
        at_h, v_h, v_l, out, nullptr, nullptr, nullptr,
        S_, S_, NHD_, NHD_,
        (size_t)S_ * S_, (size_t)S_ * NHD_, (size_t)S_ * NHD_);
}